// round 2
// baseline (speedup 1.0000x reference)
#include <cuda_runtime.h>
#include <cuda_bf16.h>
#include <math.h>

// Problem constants
#define NSEQ 2048
#define DIM  1024
#define NH   16
#define HD   64
#define NF   64      // M features
#define CH   64      // chunk size
#define NCH  32      // NSEQ / CH

// ---------------- device scratch (no allocations allowed) ----------------
__device__ float g_q[NSEQ * DIM];
__device__ float g_k[NSEQ * DIM];
__device__ float g_v[NSEQ * DIM];
__device__ float g_phiq[NH * NSEQ * NF];
__device__ float g_phik[NH * NSEQ * NF];
__device__ float g_S [NH * NCH * NF * HD];   // per-chunk KV sums
__device__ float g_P [NH * NCH * NF * HD];   // exclusive prefixes
__device__ float g_KS[NH * NCH * NF];
__device__ float g_KP[NH * NCH * NF];
__device__ float g_att[NSEQ * DIM];

// ---------------- SGEMM: C[n][o] = sum_k X[n][k] * W[o][k] (+bias) -------
#define BM 128
#define BN 64
#define BK 16

__global__ __launch_bounds__(256) void sgemm_nt(
    const float* __restrict__ X, const float* __restrict__ W,
    const float* __restrict__ bias, float* __restrict__ C,
    int Nrows, int K, int Ocols)
{
    __shared__ float As[BK][BM + 4];
    __shared__ float Bs[BK][BN + 4];

    int t  = threadIdx.x;
    int n0 = blockIdx.y * BM;
    int o0 = blockIdx.x * BN;
    int tx = t & 15;   // o dir (4 cols each)
    int ty = t >> 4;   // n dir (8 rows each)

    float acc[8][4];
#pragma unroll
    for (int i = 0; i < 8; i++)
#pragma unroll
        for (int j = 0; j < 4; j++) acc[i][j] = 0.f;

    for (int k0 = 0; k0 < K; k0 += BK) {
        // A tile: 128x16 = 512 float4, 2 per thread
#pragma unroll
        for (int r = 0; r < 2; r++) {
            int id  = t + 256 * r;
            int row = id >> 2;
            int c4  = (id & 3) << 2;
            float4 va = *(const float4*)(X + (size_t)(n0 + row) * K + k0 + c4);
            As[c4 + 0][row] = va.x; As[c4 + 1][row] = va.y;
            As[c4 + 2][row] = va.z; As[c4 + 3][row] = va.w;
        }
        // B tile: 64x16 = 256 float4, 1 per thread
        {
            int row = t >> 2;
            int c4  = (t & 3) << 2;
            float4 vb = *(const float4*)(W + (size_t)(o0 + row) * K + k0 + c4);
            Bs[c4 + 0][row] = vb.x; Bs[c4 + 1][row] = vb.y;
            Bs[c4 + 2][row] = vb.z; Bs[c4 + 3][row] = vb.w;
        }
        __syncthreads();
#pragma unroll
        for (int kk = 0; kk < BK; kk++) {
            float4 a0 = *(const float4*)&As[kk][ty * 8 + 0];
            float4 a1 = *(const float4*)&As[kk][ty * 8 + 4];
            float4 b  = *(const float4*)&Bs[kk][tx * 4];
            float a[8] = {a0.x, a0.y, a0.z, a0.w, a1.x, a1.y, a1.z, a1.w};
#pragma unroll
            for (int i = 0; i < 8; i++) {
                acc[i][0] += a[i] * b.x; acc[i][1] += a[i] * b.y;
                acc[i][2] += a[i] * b.z; acc[i][3] += a[i] * b.w;
            }
        }
        __syncthreads();
    }

    float4 bb = make_float4(0.f, 0.f, 0.f, 0.f);
    if (bias) bb = *(const float4*)(bias + o0 + tx * 4);
#pragma unroll
    for (int i = 0; i < 8; i++) {
        int n = n0 + ty * 8 + i;
        float4 v;
        v.x = acc[i][0] + bb.x; v.y = acc[i][1] + bb.y;
        v.z = acc[i][2] + bb.z; v.w = acc[i][3] + bb.w;
        *(float4*)(C + (size_t)n * Ocols + o0 + tx * 4) = v;
    }
}

// ---------------- phi: [H,N,M] = exp(q @ omega^T - 0.5||q||^2)/8 ---------
__global__ __launch_bounds__(256) void phi_kernel(
    const float* __restrict__ qk, const float* __restrict__ omega,
    float* __restrict__ phi)
{
    __shared__ float om[NF][HD + 1];
    __shared__ float qs[4][HD];
    int h  = blockIdx.y;
    int tx = threadIdx.x;   // 0..63  -> feature m
    int ty = threadIdx.y;   // 0..3   -> row within block
    int t  = ty * 64 + tx;
    for (int idx = t; idx < NF * HD; idx += 256)
        om[idx >> 6][idx & 63] = omega[idx];
    int n = blockIdx.x * 4 + ty;
    qs[ty][tx] = qk[(size_t)n * DIM + h * HD + tx];
    __syncthreads();

    float proj = 0.f, sq = 0.f;
#pragma unroll
    for (int d = 0; d < HD; d++) {
        float qd = qs[ty][d];
        proj += qd * om[tx][d];
        sq   += qd * qd;
    }
    phi[((size_t)h * NSEQ + n) * NF + tx] = expf(proj - 0.5f * sq) * 0.125f;
}

// ---------------- per-chunk KV sums: S[m][d] = sum_i phik[i][m] v[i][d] --
__global__ __launch_bounds__(256) void chunk_sum_kernel(
    const float* __restrict__ phik, const float* __restrict__ v,
    float* __restrict__ S, float* __restrict__ KS)
{
    int h = blockIdx.x >> 5;
    int c = blockIdx.x & 31;
    int n0 = c * CH;
    __shared__ float pk[CH][NF];        // [i][m]
    __shared__ float vs[CH][HD + 1];    // [i][d]
    int t = threadIdx.x;
    for (int idx = t; idx < CH * NF; idx += 256) {
        int i = idx >> 6, j = idx & 63;
        pk[i][j] = phik[((size_t)h * NSEQ + n0 + i) * NF + j];
        vs[i][j] = v[(size_t)(n0 + i) * DIM + h * HD + j];
    }
    __syncthreads();

    int m  = t >> 2;
    int d0 = (t & 3) << 4;
    float acc[16];
#pragma unroll
    for (int dd = 0; dd < 16; dd++) acc[dd] = 0.f;
    float ks = 0.f;
    for (int i = 0; i < CH; i++) {
        float kf = pk[i][m];
        ks += kf;
#pragma unroll
        for (int dd = 0; dd < 16; dd++) acc[dd] += kf * vs[i][d0 + dd];
    }
    float* Sp = S + (size_t)blockIdx.x * (NF * HD) + m * HD + d0;
#pragma unroll
    for (int dd = 0; dd < 16; dd += 4)
        *(float4*)(Sp + dd) = make_float4(acc[dd], acc[dd+1], acc[dd+2], acc[dd+3]);
    if ((t & 3) == 0) KS[(size_t)blockIdx.x * NF + m] = ks;
}

// ---------------- exclusive scan over chunks (per head) ------------------
__global__ __launch_bounds__(256) void scan_kernel(
    const float* __restrict__ S, const float* __restrict__ KS,
    float* __restrict__ P, float* __restrict__ KP)
{
    int h = blockIdx.x;
    int t = threadIdx.x;
    float run[16];
#pragma unroll
    for (int r = 0; r < 16; r++) run[r] = 0.f;
    for (int c = 0; c < NCH; c++) {
        const float* Sp = S + ((size_t)h * NCH + c) * (NF * HD);
        float*       Pp = P + ((size_t)h * NCH + c) * (NF * HD);
#pragma unroll
        for (int r = 0; r < 16; r++) {
            int e = t + (r << 8);
            Pp[e] = run[r];
            run[r] += Sp[e];
        }
    }
    if (t < NF) {
        float rk = 0.f;
        for (int c = 0; c < NCH; c++) {
            KP[((size_t)h * NCH + c) * NF + t] = rk;
            rk += KS[((size_t)h * NCH + c) * NF + t];
        }
    }
}

// ---------------- per-chunk output -----------------------------------
// out[i][d] = phiq[i]·P[:,d] + sum_{j<=i} A[i][j] v[j][d],  A = phiq phik^T
// den[i]    = phiq[i]·kp     + sum_{j<=i} A[i][j]
__global__ __launch_bounds__(256) void chunk_out_kernel(
    const float* __restrict__ phiq, const float* __restrict__ phik,
    const float* __restrict__ v, const float* __restrict__ P,
    const float* __restrict__ KP, float* __restrict__ att)
{
    extern __shared__ float sm[];
    float* pq  = sm;                 // 64*65
    float* pkm = pq  + CH * 65;
    float* vs  = pkm + CH * 65;
    float* Ps  = vs  + CH * 65;
    float* A   = Ps  + CH * 65;
    float* kp  = A   + CH * 65;
    float* den = kp  + NF;

    int h = blockIdx.x >> 5;
    int c = blockIdx.x & 31;
    int n0 = c * CH;
    int t = threadIdx.x;

    for (int idx = t; idx < CH * NF; idx += 256) {
        int i = idx >> 6, j = idx & 63;
        pq [i * 65 + j] = phiq[((size_t)h * NSEQ + n0 + i) * NF + j];
        pkm[i * 65 + j] = phik[((size_t)h * NSEQ + n0 + i) * NF + j];
        vs [i * 65 + j] = v[(size_t)(n0 + i) * DIM + h * HD + j];
        Ps [i * 65 + j] = P[(size_t)blockIdx.x * (NF * HD) + idx];
    }
    if (t < NF) kp[t] = KP[(size_t)blockIdx.x * NF + t];
    __syncthreads();

    // Phase A: A[i][j] (lower-triangular incl. diagonal)
#pragma unroll
    for (int r = 0; r < 16; r++) {
        int idx = t + (r << 8);
        int i = idx >> 6, j = idx & 63;
        float a = 0.f;
        if (j <= i) {
#pragma unroll
            for (int m = 0; m < NF; m++) a += pq[i * 65 + m] * pkm[j * 65 + m];
        }
        A[i * 65 + j] = a;
    }
    __syncthreads();

    // Phase B
    int i  = t >> 2;
    int d0 = (t & 3) << 4;
    float acc[16];
#pragma unroll
    for (int dd = 0; dd < 16; dd++) acc[dd] = 0.f;
    for (int m = 0; m < NF; m++) {
        float q = pq[i * 65 + m];
#pragma unroll
        for (int dd = 0; dd < 16; dd++) acc[dd] += q * Ps[m * 65 + d0 + dd];
    }
    if ((t & 3) == 0) {
        float s = 0.f;
        for (int m = 0; m < NF; m++) s += pq[i * 65 + m] * kp[m];
        for (int j = 0; j <= i; j++) s += A[i * 65 + j];
        den[i] = s;
    }
    for (int j = 0; j <= i; j++) {
        float a = A[i * 65 + j];
#pragma unroll
        for (int dd = 0; dd < 16; dd++) acc[dd] += a * vs[j * 65 + d0 + dd];
    }
    __syncthreads();
    float zi = 1.0f / (den[i] + 1e-6f);
    float* op = att + (size_t)(n0 + i) * DIM + h * HD + d0;
#pragma unroll
    for (int dd = 0; dd < 16; dd++) op[dd] = acc[dd] * zi;
}

// ---------------- host launch --------------------------------------------
extern "C" void kernel_launch(void* const* d_in, const int* in_sizes, int n_in,
                              void* d_out, int out_size)
{
    const float* x     = (const float*)d_in[0];
    const float* omega = (const float*)d_in[1];
    const float* wq    = (const float*)d_in[2];
    const float* wk    = (const float*)d_in[3];
    const float* wv    = (const float*)d_in[4];
    const float* wo    = (const float*)d_in[5];
    const float* bo    = (const float*)d_in[6];
    float* out = (float*)d_out;

    float *q, *k, *v, *phiq, *phik, *S, *P, *KS, *KP, *att;
    cudaGetSymbolAddress((void**)&q,    g_q);
    cudaGetSymbolAddress((void**)&k,    g_k);
    cudaGetSymbolAddress((void**)&v,    g_v);
    cudaGetSymbolAddress((void**)&phiq, g_phiq);
    cudaGetSymbolAddress((void**)&phik, g_phik);
    cudaGetSymbolAddress((void**)&S,    g_S);
    cudaGetSymbolAddress((void**)&P,    g_P);
    cudaGetSymbolAddress((void**)&KS,   g_KS);
    cudaGetSymbolAddress((void**)&KP,   g_KP);
    cudaGetSymbolAddress((void**)&att,  g_att);

    const int smem_out = (5 * CH * 65 + NF + CH) * sizeof(float);
    cudaFuncSetAttribute(chunk_out_kernel,
                         cudaFuncAttributeMaxDynamicSharedMemorySize, smem_out);

    dim3 ggrid(DIM / BN, NSEQ / BM);
    sgemm_nt<<<ggrid, 256>>>(x, wq, nullptr, q, NSEQ, DIM, DIM);
    sgemm_nt<<<ggrid, 256>>>(x, wk, nullptr, k, NSEQ, DIM, DIM);
    sgemm_nt<<<ggrid, 256>>>(x, wv, nullptr, v, NSEQ, DIM, DIM);

    dim3 pgrid(NSEQ / 4, NH);
    dim3 pblk(64, 4);
    phi_kernel<<<pgrid, pblk>>>(q, omega, phiq);
    phi_kernel<<<pgrid, pblk>>>(k, omega, phik);

    chunk_sum_kernel<<<NH * NCH, 256>>>(phik, v, S, KS);
    scan_kernel<<<NH, 256>>>(S, KS, P, KP);
    chunk_out_kernel<<<NH * NCH, 256, smem_out>>>(phiq, phik, v, P, KP, att);

    sgemm_nt<<<ggrid, 256>>>(att, wo, bo, out, NSEQ, DIM, DIM);
}

// round 6
// speedup vs baseline: 3.0108x; 3.0108x over previous
#include <cuda_runtime.h>
#include <cuda_bf16.h>
#include <math.h>
#include <stdint.h>

// Problem constants
#define NSEQ 2048
#define DIM  1024
#define NH   16
#define HD   64
#define NF   64      // M features
#define CH   64      // chunk size
#define NCH  32      // NSEQ / CH

// ---------------- device scratch (no allocations allowed) ----------------
__device__ float g_q[NSEQ * DIM];
__device__ float g_k[NSEQ * DIM];
__device__ float g_v[NSEQ * DIM];
__device__ float g_phiq[NH * NSEQ * NF];
__device__ float g_phik[NH * NSEQ * NF];
__device__ float g_S [NH * NCH * NF * HD];   // per-chunk KV sums
__device__ float g_P [NH * NCH * NF * HD];   // exclusive prefixes
__device__ float g_KS[NH * NCH * NF];
__device__ float g_KP[NH * NCH * NF];
__device__ float g_att[NSEQ * DIM];

// ---------------- helpers -------------------------------------------------
__device__ __forceinline__ uint32_t smem_u32(const void* p) {
    uint32_t a;
    asm("{ .reg .u64 t; cvta.to.shared.u64 t, %1; cvt.u32.u64 %0, t; }"
        : "=r"(a) : "l"(p));
    return a;
}

__device__ __forceinline__ uint32_t f2tf32(float x) {
    uint32_t r;
    asm("cvt.rna.tf32.f32 %0, %1;" : "=r"(r) : "f"(x));
    return r;
}

__device__ __forceinline__ void mma_tf32(float* c, const uint32_t* a, const uint32_t* b) {
    asm volatile(
        "mma.sync.aligned.m16n8k8.row.col.f32.tf32.tf32.f32 "
        "{%0,%1,%2,%3}, {%4,%5,%6,%7}, {%8,%9}, {%0,%1,%2,%3};"
        : "+f"(c[0]), "+f"(c[1]), "+f"(c[2]), "+f"(c[3])
        : "r"(a[0]), "r"(a[1]), "r"(a[2]), "r"(a[3]),
          "r"(b[0]), "r"(b[1]));
}

__device__ __forceinline__ void cp_async16(uint32_t sa, const void* g) {
    asm volatile("cp.async.ca.shared.global [%0], [%1], 16;" :: "r"(sa), "l"(g));
}
__device__ __forceinline__ void cp_commit() {
    asm volatile("cp.async.commit_group;" ::: "memory");
}
__device__ __forceinline__ void cp_wait0() {
    asm volatile("cp.async.wait_group 0;" ::: "memory");
}

// ---------------- tf32 mma.sync GEMM: C[n][o] = X[n][:]·W[o][:] (+bias) --
// 128x128 CTA tile, BK=32, 8 warps (2x4), warp tile 64x32, double-buffered
// cp.async SMEM. SMEM row stride 36 floats: 144B (16B-aligned for cp.async)
// and conflict-free for the m16n8k8 fragment pattern (36 mod 32 = 4).
#define GEMM_THREADS 256
#define GSTRIDE 36
#define MAT_BYTES (128 * GSTRIDE * 4)        // 18432
#define GEMM_SMEM (4 * MAT_BYTES)            // 73728

__global__ __launch_bounds__(GEMM_THREADS, 1)
void tc_gemm(const float* __restrict__ X, const float* __restrict__ W,
             const float* __restrict__ bias, float* __restrict__ C)
{
    extern __shared__ __align__(16) char smem[];
    const uint32_t sb = smem_u32(smem);
    const int t    = threadIdx.x;
    const int wid  = t >> 5;
    const int lane = t & 31;
    const int g    = lane >> 2;     // group id (row within fragment)
    const int tid4 = lane & 3;      // thread in group
    const int wm   = (wid >> 2) * 64;   // warp m offset in tile
    const int wn   = (wid & 3) * 32;    // warp n offset in tile
    const int n0   = blockIdx.y * 128;
    const int o0   = blockIdx.x * 128;

    // buffer offsets: A0, B0, A1, B1
    auto aoff = [&](int b) { return (uint32_t)(b * 2 * MAT_BYTES); };
    auto boff = [&](int b) { return (uint32_t)(b * 2 * MAT_BYTES + MAT_BYTES); };

    // issue loads for k-tile `kt` into buffer `b`
    auto load_tile = [&](int kt, int b) {
        int k0 = kt * 32;
#pragma unroll
        for (int r = 0; r < 4; r++) {
            int id  = t + 256 * r;       // 0..1023
            int row = id >> 3;           // 0..127
            int c4  = (id & 7) << 2;     // 0,4,...,28
            uint32_t so = (uint32_t)((row * GSTRIDE + c4) * 4);
            cp_async16(sb + aoff(b) + so, X + (size_t)(n0 + row) * DIM + k0 + c4);
            cp_async16(sb + boff(b) + so, W + (size_t)(o0 + row) * DIM + k0 + c4);
        }
        cp_commit();
    };

    float acc[4][4][4];
#pragma unroll
    for (int i = 0; i < 4; i++)
#pragma unroll
        for (int j = 0; j < 4; j++)
#pragma unroll
            for (int r = 0; r < 4; r++) acc[i][j][r] = 0.f;

    load_tile(0, 0);
    cp_wait0();
    __syncthreads();

    int buf = 0;
    for (int it = 0; it < 32; ++it) {
        if (it + 1 < 32) load_tile(it + 1, buf ^ 1);

        const float* As = (const float*)(smem + aoff(buf));
        const float* Bs = (const float*)(smem + boff(buf));
#pragma unroll
        for (int ks = 0; ks < 4; ks++) {
            int k = ks * 8;
            uint32_t a[4][4];
#pragma unroll
            for (int mf = 0; mf < 4; mf++) {
                int r0 = wm + mf * 16 + g;
                a[mf][0] = f2tf32(As[r0 * GSTRIDE + k + tid4]);
                a[mf][1] = f2tf32(As[(r0 + 8) * GSTRIDE + k + tid4]);
                a[mf][2] = f2tf32(As[r0 * GSTRIDE + k + tid4 + 4]);
                a[mf][3] = f2tf32(As[(r0 + 8) * GSTRIDE + k + tid4 + 4]);
            }
            uint32_t b[4][2];
#pragma unroll
            for (int nf = 0; nf < 4; nf++) {
                int c0 = wn + nf * 8 + g;
                b[nf][0] = f2tf32(Bs[c0 * GSTRIDE + k + tid4]);
                b[nf][1] = f2tf32(Bs[c0 * GSTRIDE + k + tid4 + 4]);
            }
#pragma unroll
            for (int mf = 0; mf < 4; mf++)
#pragma unroll
                for (int nf = 0; nf < 4; nf++)
                    mma_tf32(acc[mf][nf], a[mf], b[nf]);
        }

        if (it + 1 < 32) {
            cp_wait0();
            __syncthreads();
            buf ^= 1;
        }
    }

    // epilogue: direct float2 stores
#pragma unroll
    for (int nf = 0; nf < 4; nf++) {
        int col = o0 + wn + nf * 8 + tid4 * 2;
        float2 bb = make_float2(0.f, 0.f);
        if (bias) bb = *(const float2*)(bias + col);
#pragma unroll
        for (int mf = 0; mf < 4; mf++) {
            int row = n0 + wm + mf * 16 + g;
            float2 v0, v1;
            v0.x = acc[mf][nf][0] + bb.x; v0.y = acc[mf][nf][1] + bb.y;
            v1.x = acc[mf][nf][2] + bb.x; v1.y = acc[mf][nf][3] + bb.y;
            *(float2*)(C + (size_t)row * DIM + col)       = v0;
            *(float2*)(C + (size_t)(row + 8) * DIM + col) = v1;
        }
    }
}

// ---------------- phi: [H,N,M] = exp(q @ omega^T - 0.5||q||^2)/8 ---------
__global__ __launch_bounds__(256) void phi_kernel(
    const float* __restrict__ qk, const float* __restrict__ omega,
    float* __restrict__ phi)
{
    __shared__ float om[NF][HD + 1];
    __shared__ float qs[4][HD];
    int h  = blockIdx.y;
    int tx = threadIdx.x;   // 0..63  -> feature m
    int ty = threadIdx.y;   // 0..3   -> row within block
    int t  = ty * 64 + tx;
    for (int idx = t; idx < NF * HD; idx += 256)
        om[idx >> 6][idx & 63] = omega[idx];
    int n = blockIdx.x * 4 + ty;
    qs[ty][tx] = qk[(size_t)n * DIM + h * HD + tx];
    __syncthreads();

    float proj = 0.f, sq = 0.f;
#pragma unroll
    for (int d = 0; d < HD; d++) {
        float qd = qs[ty][d];
        proj += qd * om[tx][d];
        sq   += qd * qd;
    }
    phi[((size_t)h * NSEQ + n) * NF + tx] = expf(proj - 0.5f * sq) * 0.125f;
}

// ---------------- per-chunk KV sums: S[m][d] = sum_i phik[i][m] v[i][d] --
__global__ __launch_bounds__(256) void chunk_sum_kernel(
    const float* __restrict__ phik, const float* __restrict__ v,
    float* __restrict__ S, float* __restrict__ KS)
{
    int h = blockIdx.x >> 5;
    int c = blockIdx.x & 31;
    int n0 = c * CH;
    __shared__ float pk[CH][NF];        // [i][m]
    __shared__ float vs[CH][HD + 1];    // [i][d]
    int t = threadIdx.x;
    for (int idx = t; idx < CH * NF; idx += 256) {
        int i = idx >> 6, j = idx & 63;
        pk[i][j] = phik[((size_t)h * NSEQ + n0 + i) * NF + j];
        vs[i][j] = v[(size_t)(n0 + i) * DIM + h * HD + j];
    }
    __syncthreads();

    int m  = t >> 2;
    int d0 = (t & 3) << 4;
    float acc[16];
#pragma unroll
    for (int dd = 0; dd < 16; dd++) acc[dd] = 0.f;
    float ks = 0.f;
    for (int i = 0; i < CH; i++) {
        float kf = pk[i][m];
        ks += kf;
#pragma unroll
        for (int dd = 0; dd < 16; dd++) acc[dd] += kf * vs[i][d0 + dd];
    }
    float* Sp = S + (size_t)blockIdx.x * (NF * HD) + m * HD + d0;
#pragma unroll
    for (int dd = 0; dd < 16; dd += 4)
        *(float4*)(Sp + dd) = make_float4(acc[dd], acc[dd+1], acc[dd+2], acc[dd+3]);
    if ((t & 3) == 0) KS[(size_t)blockIdx.x * NF + m] = ks;
}

// ---------------- exclusive scan over chunks (per head) ------------------
__global__ __launch_bounds__(256) void scan_kernel(
    const float* __restrict__ S, const float* __restrict__ KS,
    float* __restrict__ P, float* __restrict__ KP)
{
    int h = blockIdx.x;
    int t = threadIdx.x;
    float run[16];
#pragma unroll
    for (int r = 0; r < 16; r++) run[r] = 0.f;
    for (int c = 0; c < NCH; c++) {
        const float* Sp = S + ((size_t)h * NCH + c) * (NF * HD);
        float*       Pp = P + ((size_t)h * NCH + c) * (NF * HD);
#pragma unroll
        for (int r = 0; r < 16; r++) {
            int e = t + (r << 8);
            Pp[e] = run[r];
            run[r] += Sp[e];
        }
    }
    if (t < NF) {
        float rk = 0.f;
        for (int c = 0; c < NCH; c++) {
            KP[((size_t)h * NCH + c) * NF + t] = rk;
            rk += KS[((size_t)h * NCH + c) * NF + t];
        }
    }
}

// ---------------- per-chunk output -----------------------------------
__global__ __launch_bounds__(256) void chunk_out_kernel(
    const float* __restrict__ phiq, const float* __restrict__ phik,
    const float* __restrict__ v, const float* __restrict__ P,
    const float* __restrict__ KP, float* __restrict__ att)
{
    extern __shared__ float sm[];
    float* pq  = sm;                 // 64*65
    float* pkm = pq  + CH * 65;
    float* vs  = pkm + CH * 65;
    float* Ps  = vs  + CH * 65;
    float* A   = Ps  + CH * 65;
    float* kp  = A   + CH * 65;
    float* den = kp  + NF;

    int h = blockIdx.x >> 5;
    int c = blockIdx.x & 31;
    int n0 = c * CH;
    int t = threadIdx.x;

    for (int idx = t; idx < CH * NF; idx += 256) {
        int i = idx >> 6, j = idx & 63;
        pq [i * 65 + j] = phiq[((size_t)h * NSEQ + n0 + i) * NF + j];
        pkm[i * 65 + j] = phik[((size_t)h * NSEQ + n0 + i) * NF + j];
        vs [i * 65 + j] = v[(size_t)(n0 + i) * DIM + h * HD + j];
        Ps [i * 65 + j] = P[(size_t)blockIdx.x * (NF * HD) + idx];
    }
    if (t < NF) kp[t] = KP[(size_t)blockIdx.x * NF + t];
    __syncthreads();

    // Phase A: A[i][j] (lower-triangular incl. diagonal)
#pragma unroll
    for (int r = 0; r < 16; r++) {
        int idx = t + (r << 8);
        int i = idx >> 6, j = idx & 63;
        float a = 0.f;
        if (j <= i) {
#pragma unroll
            for (int m = 0; m < NF; m++) a += pq[i * 65 + m] * pkm[j * 65 + m];
        }
        A[i * 65 + j] = a;
    }
    __syncthreads();

    // Phase B
    int i  = t >> 2;
    int d0 = (t & 3) << 4;
    float acc[16];
#pragma unroll
    for (int dd = 0; dd < 16; dd++) acc[dd] = 0.f;
    for (int m = 0; m < NF; m++) {
        float q = pq[i * 65 + m];
#pragma unroll
        for (int dd = 0; dd < 16; dd++) acc[dd] += q * Ps[m * 65 + d0 + dd];
    }
    if ((t & 3) == 0) {
        float s = 0.f;
        for (int m = 0; m < NF; m++) s += pq[i * 65 + m] * kp[m];
        for (int j = 0; j <= i; j++) s += A[i * 65 + j];
        den[i] = s;
    }
    for (int j = 0; j <= i; j++) {
        float a = A[i * 65 + j];
#pragma unroll
        for (int dd = 0; dd < 16; dd++) acc[dd] += a * vs[j * 65 + d0 + dd];
    }
    __syncthreads();
    float zi = 1.0f / (den[i] + 1e-6f);
    float* op = att + (size_t)(n0 + i) * DIM + h * HD + d0;
#pragma unroll
    for (int dd = 0; dd < 16; dd++) op[dd] = acc[dd] * zi;
}

// ---------------- host launch --------------------------------------------
extern "C" void kernel_launch(void* const* d_in, const int* in_sizes, int n_in,
                              void* d_out, int out_size)
{
    const float* x     = (const float*)d_in[0];
    const float* omega = (const float*)d_in[1];
    const float* wq    = (const float*)d_in[2];
    const float* wk    = (const float*)d_in[3];
    const float* wv    = (const float*)d_in[4];
    const float* wo    = (const float*)d_in[5];
    const float* bo    = (const float*)d_in[6];
    float* out = (float*)d_out;

    float *q, *k, *v, *phiq, *phik, *S, *P, *KS, *KP, *att;
    cudaGetSymbolAddress((void**)&q,    g_q);
    cudaGetSymbolAddress((void**)&k,    g_k);
    cudaGetSymbolAddress((void**)&v,    g_v);
    cudaGetSymbolAddress((void**)&phiq, g_phiq);
    cudaGetSymbolAddress((void**)&phik, g_phik);
    cudaGetSymbolAddress((void**)&S,    g_S);
    cudaGetSymbolAddress((void**)&P,    g_P);
    cudaGetSymbolAddress((void**)&KS,   g_KS);
    cudaGetSymbolAddress((void**)&KP,   g_KP);
    cudaGetSymbolAddress((void**)&att,  g_att);

    const int smem_out = (5 * CH * 65 + NF + CH) * sizeof(float);
    cudaFuncSetAttribute(chunk_out_kernel,
                         cudaFuncAttributeMaxDynamicSharedMemorySize, smem_out);
    cudaFuncSetAttribute(tc_gemm,
                         cudaFuncAttributeMaxDynamicSharedMemorySize, GEMM_SMEM);

    dim3 ggrid(DIM / 128, NSEQ / 128);   // 8 x 16 = 128 CTAs
    tc_gemm<<<ggrid, GEMM_THREADS, GEMM_SMEM>>>(x, wq, nullptr, q);
    tc_gemm<<<ggrid, GEMM_THREADS, GEMM_SMEM>>>(x, wk, nullptr, k);
    tc_gemm<<<ggrid, GEMM_THREADS, GEMM_SMEM>>>(x, wv, nullptr, v);

    dim3 pgrid(NSEQ / 4, NH);
    dim3 pblk(64, 4);
    phi_kernel<<<pgrid, pblk>>>(q, omega, phiq);
    phi_kernel<<<pgrid, pblk>>>(k, omega, phik);

    chunk_sum_kernel<<<NH * NCH, 256>>>(phik, v, S, KS);
    scan_kernel<<<NH, 256>>>(S, KS, P, KP);
    chunk_out_kernel<<<NH * NCH, 256, smem_out>>>(phiq, phik, v, P, KP, att);

    tc_gemm<<<ggrid, GEMM_THREADS, GEMM_SMEM>>>(att, wo, bo, out);
}